// round 7
// baseline (speedup 1.0000x reference)
#include <cuda_runtime.h>
#include <math.h>

#define NN   20000
#define NE   400000
#define DIMN 128
#define NB16 16
#define ZD16 16

// ---------------- scratch (static device globals; no runtime allocation) ----------------
__device__ float d_z0[NN * ZD16];          // species embedding  [20000,16]
__device__ float d_c[NE * NB16];           // per-edge coeffs sw*s  [400000,16]
__device__ int   d_counts[NN];
__device__ int   d_offsets[NN + 1];
__device__ int   d_cursor[NN];
__device__ int   d_sorted[NE];             // edge ids sorted by src (CSR)
__device__ float d_zself[NN * DIMN];
__device__ float d_G[NN * NB16 * DIMN];    // gathered g [20000,16,128] (layer0 uses [20000,256])
__device__ float d_zi[NN * DIMN];
__device__ float d_h[NN * DIMN];

// ---------------- small kernels ----------------
__global__ void embed_kernel(const int* __restrict__ species, const float* __restrict__ Z) {
    int i = blockIdx.x * blockDim.x + threadIdx.x;
    if (i < NN * ZD16) {
        int n = i >> 4, d = i & 15;
        d_z0[i] = Z[species[n] * ZD16 + d];
    }
}

__global__ void coeff_kernel(const float* __restrict__ dist, const float* __restrict__ sw) {
    int e = blockIdx.x * blockDim.x + threadIdx.x;
    if (e >= NE) return;
    float rinv = 1.0f / dist[e];
    float swv = sw[e];
    const float mu0 = 0.2f;
    const float step = 0.8f / 15.0f;
    const float inv_sigma = 15.0f / 0.8f;
#pragma unroll
    for (int b = 0; b < 16; b++) {
        float t = (rinv - (mu0 + (float)b * step)) * inv_sigma;
        d_c[e * 16 + b] = swv * expf(-0.5f * t * t);
    }
}

__global__ void zero_counts_kernel() {
    int i = blockIdx.x * blockDim.x + threadIdx.x;
    if (i < NN) d_counts[i] = 0;
}

__global__ void hist_kernel(const int* __restrict__ esrc) {
    int e = blockIdx.x * blockDim.x + threadIdx.x;
    if (e < NE) atomicAdd(&d_counts[esrc[e]], 1);
}

// single-block exclusive scan over d_counts -> d_offsets, d_cursor
__global__ void scan_kernel() {
    __shared__ int warp_sums[32];
    __shared__ int s_carry;
    int t = threadIdx.x;
    if (t == 0) s_carry = 0;
    __syncthreads();
    for (int base = 0; base < NN; base += 1024) {
        int i = base + t;
        int v = (i < NN) ? d_counts[i] : 0;
        int x = v;
#pragma unroll
        for (int o = 1; o < 32; o <<= 1) {
            int y = __shfl_up_sync(0xffffffffu, x, o);
            if ((t & 31) >= o) x += y;
        }
        if ((t & 31) == 31) warp_sums[t >> 5] = x;
        __syncthreads();
        if (t < 32) {
            int w = warp_sums[t];
#pragma unroll
            for (int o = 1; o < 32; o <<= 1) {
                int y = __shfl_up_sync(0xffffffffu, w, o);
                if (t >= o) w += y;
            }
            warp_sums[t] = w;
        }
        __syncthreads();
        int incl = x + ((t >= 32) ? warp_sums[(t >> 5) - 1] : 0);
        int excl = s_carry + incl - v;
        if (i < NN) {
            d_offsets[i] = excl;
            d_cursor[i] = excl;
        }
        __syncthreads();
        if (t == 1023) s_carry += incl;
        __syncthreads();
    }
    if (t == 0) d_offsets[NN] = s_carry;
}

__global__ void scatter_kernel(const int* __restrict__ esrc) {
    int e = blockIdx.x * blockDim.x + threadIdx.x;
    if (e < NE) {
        int pos = atomicAdd(&d_cursor[esrc[e]], 1);
        d_sorted[pos] = e;
    }
}

// ---------------- edge gather kernels (build G) ----------------
// layer 0: g0[n, b, d16] ; one block per node, 256 threads = one (b,d) each
__global__ void gather0_kernel(const int* __restrict__ edst) {
    int n = blockIdx.x;
    int t = threadIdx.x;
    __shared__ float cs[16];
    __shared__ float zs[16];
    int b = t >> 4, d = t & 15;
    float acc = 0.0f;
    int beg = d_offsets[n], end = d_offsets[n + 1];
    for (int i = beg; i < end; i++) {
        int e = d_sorted[i];
        __syncthreads();
        if (t < 16) cs[t] = d_c[e * 16 + t];
        else if (t < 32) zs[t - 16] = d_z0[edst[e] * ZD16 + (t - 16)];
        __syncthreads();
        acc += cs[b] * zs[d];
    }
    d_G[n * 256 + t] = acc;
}

// layer 1: g1[n, b, d128] ; one block per node, 128 threads (thread owns d), 16 accs over b
__global__ void gather1_kernel(const int* __restrict__ edst) {
    int n = blockIdx.x;
    int t = threadIdx.x;
    __shared__ float cs[16];
    float acc[16];
#pragma unroll
    for (int b = 0; b < 16; b++) acc[b] = 0.0f;
    int beg = d_offsets[n], end = d_offsets[n + 1];
    for (int i = beg; i < end; i++) {
        int e = d_sorted[i];
        __syncthreads();
        if (t < 16) cs[t] = d_c[e * 16 + t];
        __syncthreads();
        float zd = d_zi[edst[e] * DIMN + t];
#pragma unroll
        for (int b = 0; b < 16; b++) acc[b] += cs[b] * zd;
    }
    float* gp = &d_G[(size_t)n * 2048 + t];
#pragma unroll
    for (int b = 0; b < 16; b++) gp[b * 128] = acc[b];
}

// ---------------- tiled fp32 GEMM: C[M,128] = A[M,K] @ B[K,128] + epilogue ----------------
#define M_BIAS 0  // C = AB + bias
#define M_EDGE 1  // C = silu(AB + D)
#define M_ONA  2  // C = silu(AB + bias)
#define M_ONB  3  // C = D + AB + bias

__device__ __forceinline__ float silu_f(float x) { return x / (1.0f + expf(-x)); }

template <int MODE>
__global__ void __launch_bounds__(256) gemm128(const float* __restrict__ A,
                                               const float* __restrict__ B,
                                               const float* __restrict__ D,
                                               const float* __restrict__ bias,
                                               float* __restrict__ C, int M, int K) {
    __shared__ float As[16][64];
    __shared__ float Bs[16][128];
    int tid = threadIdx.x;
    int m0 = blockIdx.x * 64;
    int tm = tid >> 4, tn = tid & 15;
    int ar = tid >> 2, ac = (tid & 3) << 2;
    int br = tid >> 5, bc = (tid & 31) << 2;
    int arow = m0 + ar;

    float acc[4][8];
#pragma unroll
    for (int r = 0; r < 4; r++)
#pragma unroll
        for (int c = 0; c < 8; c++) acc[r][c] = 0.0f;

    for (int k0 = 0; k0 < K; k0 += 16) {
        float4 av = make_float4(0.f, 0.f, 0.f, 0.f);
        if (arow < M) av = *reinterpret_cast<const float4*>(&A[(size_t)arow * K + k0 + ac]);
        float4 bv0 = *reinterpret_cast<const float4*>(&B[(size_t)(k0 + br) * 128 + bc]);
        float4 bv1 = *reinterpret_cast<const float4*>(&B[(size_t)(k0 + br + 8) * 128 + bc]);
        __syncthreads();
        As[ac + 0][ar] = av.x;
        As[ac + 1][ar] = av.y;
        As[ac + 2][ar] = av.z;
        As[ac + 3][ar] = av.w;
        *reinterpret_cast<float4*>(&Bs[br][bc]) = bv0;
        *reinterpret_cast<float4*>(&Bs[br + 8][bc]) = bv1;
        __syncthreads();
#pragma unroll
        for (int kk = 0; kk < 16; kk++) {
            float4 a = *reinterpret_cast<const float4*>(&As[kk][tm << 2]);
            float4 p = *reinterpret_cast<const float4*>(&Bs[kk][tn << 3]);
            float4 q = *reinterpret_cast<const float4*>(&Bs[kk][(tn << 3) + 4]);
            float a4[4] = {a.x, a.y, a.z, a.w};
            float b8[8] = {p.x, p.y, p.z, p.w, q.x, q.y, q.z, q.w};
#pragma unroll
            for (int r = 0; r < 4; r++)
#pragma unroll
                for (int c = 0; c < 8; c++) acc[r][c] += a4[r] * b8[c];
        }
    }

#pragma unroll
    for (int r = 0; r < 4; r++) {
        int row = m0 + (tm << 2) + r;
        if (row >= M) continue;
#pragma unroll
        for (int c = 0; c < 8; c++) {
            int col = (tn << 3) + c;
            float v = acc[r][c];
            if (MODE == M_BIAS) {
                v += bias[col];
            } else if (MODE == M_EDGE) {
                v = silu_f(v + D[(size_t)row * 128 + col]);
            } else if (MODE == M_ONA) {
                v = silu_f(v + bias[col]);
            } else {
                v = D[(size_t)row * 128 + col] + v + bias[col];
            }
            C[(size_t)row * 128 + col] = v;
        }
    }
}

// ---------------- output stores ----------------
__global__ void store_layer_kernel(float* __restrict__ out, int layer) {
    int i = blockIdx.x * blockDim.x + threadIdx.x;
    if (i < NN * DIMN) {
        int n = i >> 7, d = i & 127;
        out[NN * DIMN + n * 256 + layer * 128 + d] = d_zi[i];
    }
}

__global__ void store_final_kernel(float* __restrict__ out) {
    int i = blockIdx.x * blockDim.x + threadIdx.x;
    if (i < NN * DIMN) out[i] = d_zi[i];
}

// ---------------- launch ----------------
static void* sym_addr(const void* sym) {
    void* p = nullptr;
    cudaGetSymbolAddress(&p, sym);
    return p;
}

extern "C" void kernel_launch(void* const* d_in, const int* in_sizes, int n_in,
                              void* d_out, int out_size) {
    const int*   species = (const int*)d_in[0];
    const int*   esrc    = (const int*)d_in[1];
    const int*   edst    = (const int*)d_in[2];
    const float* dist    = (const float*)d_in[3];
    const float* sw      = (const float*)d_in[4];
    const float* Z       = (const float*)d_in[5];
    const float* Ws0     = (const float*)d_in[6];
    const float* bs0     = (const float*)d_in[7];
    const float* V0      = (const float*)d_in[8];
    const float* Ws1     = (const float*)d_in[9];
    const float* bs1     = (const float*)d_in[10];
    const float* V1      = (const float*)d_in[11];
    const float* Won_a   = (const float*)d_in[12];
    const float* bon_a   = (const float*)d_in[13];
    const float* Won_b   = (const float*)d_in[14];
    const float* bon_b   = (const float*)d_in[15];
    float* out = (float*)d_out;

    float* p_z0    = (float*)sym_addr(d_z0);
    float* p_zself = (float*)sym_addr(d_zself);
    float* p_G     = (float*)sym_addr(d_G);
    float* p_zi    = (float*)sym_addr(d_zi);
    float* p_h     = (float*)sym_addr(d_h);

    // setup (layer-independent)
    embed_kernel<<<(NN * ZD16 + 255) / 256, 256>>>(species, Z);
    coeff_kernel<<<(NE + 127) / 128, 128>>>(dist, sw);
    zero_counts_kernel<<<(NN + 255) / 256, 256>>>();
    hist_kernel<<<(NE + 255) / 256, 256>>>(esrc);
    scan_kernel<<<1, 1024>>>();
    scatter_kernel<<<(NE + 255) / 256, 256>>>(esrc);

    const int GB = (NN + 63) / 64;
    const int EL = (NN * DIMN + 255) / 256;

    // ---- layer 0 ----
    gemm128<M_BIAS><<<GB, 256>>>(p_z0, Ws0, nullptr, bs0, p_zself, NN, ZD16);
    gather0_kernel<<<NN, 256>>>(edst);
    gemm128<M_EDGE><<<GB, 256>>>(p_G, V0, p_zself, nullptr, p_zi, NN, NB16 * ZD16);
    for (int j = 0; j < 3; j++) {
        gemm128<M_ONA><<<GB, 256>>>(p_zi, Won_a + j * 16384, nullptr, bon_a + j * 128, p_h, NN, 128);
        gemm128<M_ONB><<<GB, 256>>>(p_h, Won_b + j * 16384, p_zi, bon_b + j * 128, p_zi, NN, 128);
    }
    store_layer_kernel<<<EL, 256>>>(out, 0);

    // ---- layer 1 ----
    gemm128<M_BIAS><<<GB, 256>>>(p_zi, Ws1, nullptr, bs1, p_zself, NN, 128);
    gather1_kernel<<<NN, 128>>>(edst);
    gemm128<M_EDGE><<<GB, 256>>>(p_G, V1, p_zself, nullptr, p_zi, NN, NB16 * DIMN);
    for (int j = 0; j < 3; j++) {
        gemm128<M_ONA><<<GB, 256>>>(p_zi, Won_a + (3 + j) * 16384, nullptr, bon_a + (3 + j) * 128, p_h, NN, 128);
        gemm128<M_ONB><<<GB, 256>>>(p_h, Won_b + (3 + j) * 16384, p_zi, bon_b + (3 + j) * 128, p_zi, NN, 128);
    }
    store_layer_kernel<<<EL, 256>>>(out, 1);
    store_final_kernel<<<EL, 256>>>(out);
}

// round 16
// speedup vs baseline: 1.4098x; 1.4098x over previous
#include <cuda_runtime.h>
#include <math.h>

#define NN   20000
#define NE   400000
#define DIMN 128
#define NB16 16
#define ZD16 16

// ---------------- scratch (static device globals; no runtime allocation) ----------------
__device__ float d_z0[NN * ZD16];          // species embedding  [20000,16]
__device__ float d_c[NE * NB16];           // per-edge coeffs sw*s  [400000,16]
__device__ int   d_counts[NN];
__device__ int   d_offsets[NN + 1];
__device__ int   d_cursor[NN];
__device__ int   d_sorted[NE];             // edge ids sorted by src (CSR)
__device__ float d_zself[NN * DIMN];
__device__ float d_G[NN * NB16 * DIMN];    // gathered g [20000,16,128] (layer0 uses [20000,256])
__device__ float d_zi[NN * DIMN];
__device__ float d_h[NN * DIMN];

// ---------------- small kernels ----------------
__global__ void embed_kernel(const int* __restrict__ species, const float* __restrict__ Z) {
    int i = blockIdx.x * blockDim.x + threadIdx.x;
    if (i < NN * ZD16) {
        int n = i >> 4, d = i & 15;
        d_z0[i] = Z[species[n] * ZD16 + d];
    }
}

__global__ void coeff_kernel(const float* __restrict__ dist, const float* __restrict__ sw) {
    int e = blockIdx.x * blockDim.x + threadIdx.x;
    if (e >= NE) return;
    float rinv = 1.0f / dist[e];
    float swv = sw[e];
    const float mu0 = 0.2f;
    const float step = 0.8f / 15.0f;
    const float inv_sigma = 15.0f / 0.8f;
#pragma unroll
    for (int b = 0; b < 16; b++) {
        float t = (rinv - (mu0 + (float)b * step)) * inv_sigma;
        d_c[e * 16 + b] = swv * expf(-0.5f * t * t);
    }
}

__global__ void zero_counts_kernel() {
    int i = blockIdx.x * blockDim.x + threadIdx.x;
    if (i < NN) d_counts[i] = 0;
}

__global__ void hist_kernel(const int* __restrict__ esrc) {
    int e = blockIdx.x * blockDim.x + threadIdx.x;
    if (e < NE) atomicAdd(&d_counts[esrc[e]], 1);
}

// single-block exclusive scan over d_counts -> d_offsets, d_cursor
__global__ void scan_kernel() {
    __shared__ int warp_sums[32];
    __shared__ int s_carry;
    int t = threadIdx.x;
    if (t == 0) s_carry = 0;
    __syncthreads();
    for (int base = 0; base < NN; base += 1024) {
        int i = base + t;
        int v = (i < NN) ? d_counts[i] : 0;
        int x = v;
#pragma unroll
        for (int o = 1; o < 32; o <<= 1) {
            int y = __shfl_up_sync(0xffffffffu, x, o);
            if ((t & 31) >= o) x += y;
        }
        if ((t & 31) == 31) warp_sums[t >> 5] = x;
        __syncthreads();
        if (t < 32) {
            int w = warp_sums[t];
#pragma unroll
            for (int o = 1; o < 32; o <<= 1) {
                int y = __shfl_up_sync(0xffffffffu, w, o);
                if (t >= o) w += y;
            }
            warp_sums[t] = w;
        }
        __syncthreads();
        int incl = x + ((t >= 32) ? warp_sums[(t >> 5) - 1] : 0);
        int excl = s_carry + incl - v;
        if (i < NN) {
            d_offsets[i] = excl;
            d_cursor[i] = excl;
        }
        __syncthreads();
        if (t == 1023) s_carry += incl;
        __syncthreads();
    }
    if (t == 0) d_offsets[NN] = s_carry;
}

__global__ void scatter_kernel(const int* __restrict__ esrc) {
    int e = blockIdx.x * blockDim.x + threadIdx.x;
    if (e < NE) {
        int pos = atomicAdd(&d_cursor[esrc[e]], 1);
        d_sorted[pos] = e;
    }
}

// ---------------- edge gather kernels (build G) — no smem, no per-edge syncs ----------------
// layer 0: g0[n, b, d16] ; one block per node, 256 threads = one (b,d) each
__global__ void gather0_kernel(const int* __restrict__ edst) {
    int n = blockIdx.x;
    int t = threadIdx.x;
    int b = t >> 4, d = t & 15;
    float acc = 0.0f;
    int beg = d_offsets[n], end = d_offsets[n + 1];
    for (int i = beg; i < end; i++) {
        int e = __ldg(&d_sorted[i]);
        int dst = __ldg(&edst[e]);
        acc += __ldg(&d_c[e * 16 + b]) * __ldg(&d_z0[dst * ZD16 + d]);
    }
    d_G[n * 256 + t] = acc;
}

// layer 1: g1[n, b, d128] ; one block per node, 128 threads (thread owns d), 16 accs over b
__global__ void gather1_kernel(const int* __restrict__ edst) {
    int n = blockIdx.x;
    int t = threadIdx.x;
    float acc[16];
#pragma unroll
    for (int b = 0; b < 16; b++) acc[b] = 0.0f;
    int beg = d_offsets[n], end = d_offsets[n + 1];

    int e = (beg < end) ? __ldg(&d_sorted[beg]) : 0;
    int dst = (beg < end) ? __ldg(&edst[e]) : 0;
    for (int i = beg; i < end; i++) {
        int inext = i + 1;
        int en = 0, dn = 0;
        if (inext < end) {
            en = __ldg(&d_sorted[inext]);
            dn = __ldg(&edst[en]);
        }
        const float4* cp = reinterpret_cast<const float4*>(&d_c[e * 16]);
        float4 c0 = __ldg(&cp[0]);
        float4 c1 = __ldg(&cp[1]);
        float4 c2 = __ldg(&cp[2]);
        float4 c3 = __ldg(&cp[3]);
        float zd = __ldg(&d_zi[(size_t)dst * DIMN + t]);
        acc[0]  += c0.x * zd;  acc[1]  += c0.y * zd;  acc[2]  += c0.z * zd;  acc[3]  += c0.w * zd;
        acc[4]  += c1.x * zd;  acc[5]  += c1.y * zd;  acc[6]  += c1.z * zd;  acc[7]  += c1.w * zd;
        acc[8]  += c2.x * zd;  acc[9]  += c2.y * zd;  acc[10] += c2.z * zd;  acc[11] += c2.w * zd;
        acc[12] += c3.x * zd;  acc[13] += c3.y * zd;  acc[14] += c3.z * zd;  acc[15] += c3.w * zd;
        e = en; dst = dn;
    }
    float* gp = &d_G[(size_t)n * 2048 + t];
#pragma unroll
    for (int b = 0; b < 16; b++) gp[b * 128] = acc[b];
}

// ---------------- 3xTF32 tensor-core GEMM: C[M,128] = A[M,K] @ B[K,128] + epilogue ----------------
#define M_BIAS 0  // C = AB + bias
#define M_EDGE 1  // C = silu(AB + D)
#define M_ONA  2  // C = silu(AB + bias)
#define M_ONB  3  // C = D + AB + bias

__device__ __forceinline__ float silu_f(float x) { return x / (1.0f + expf(-x)); }

__device__ __forceinline__ unsigned f2tf32(float x) {
    unsigned r;
    asm("cvt.rna.tf32.f32 %0, %1;" : "=r"(r) : "f"(x));
    return r;
}

// split: hi = tf32(x) (exact fp32 value with low mantissa zeroed), lo = tf32(x - hi)
__device__ __forceinline__ void tf32_split(float x, unsigned& hi, unsigned& lo) {
    hi = f2tf32(x);
    lo = f2tf32(x - __uint_as_float(hi));
}

__device__ __forceinline__ void mma_tf32(float* d, const unsigned* a, const unsigned* b) {
    asm volatile(
        "mma.sync.aligned.m16n8k8.row.col.f32.tf32.tf32.f32 "
        "{%0,%1,%2,%3}, {%4,%5,%6,%7}, {%8,%9}, {%0,%1,%2,%3};\n"
        : "+f"(d[0]), "+f"(d[1]), "+f"(d[2]), "+f"(d[3])
        : "r"(a[0]), "r"(a[1]), "r"(a[2]), "r"(a[3]), "r"(b[0]), "r"(b[1]));
}

// Block tile 128x128, BK=32. 8 warps in a 4x2 (m x n) grid, warp tile 32x64.
// smem k-major with stride 132 (mod-32 = 4) -> conflict-free fragment loads.
// 3xTF32: acc += Ahi*Bhi + Ahi*Blo + Alo*Bhi  (fp32-equivalent precision)
template <int MODE>
__global__ void __launch_bounds__(256) gemm_tc(const float* __restrict__ A,
                                               const float* __restrict__ B,
                                               const float* __restrict__ D,
                                               const float* __restrict__ bias,
                                               float* __restrict__ C, int M, int K) {
    __shared__ float As[32][132];   // [k][m]
    __shared__ float Bs[32][132];   // [k][n]
    int tid = threadIdx.x;
    int lane = tid & 31, warp = tid >> 5;
    int wm = warp >> 1, wn = warp & 1;
    int g = lane >> 2, c = lane & 3;
    int m0 = blockIdx.x * 128;

    float acc[2][8][4];
#pragma unroll
    for (int mf = 0; mf < 2; mf++)
#pragma unroll
        for (int nf = 0; nf < 8; nf++)
#pragma unroll
            for (int q = 0; q < 4; q++) acc[mf][nf][q] = 0.0f;

    int arow  = tid >> 1;            // 0..127
    int acol0 = (tid & 1) * 16;      // 0 / 16
    int brow  = tid >> 5;            // 0..7
    int bcol  = (tid & 31) * 4;      // 0..124

    for (int k0 = 0; k0 < K; k0 += 32) {
        float4 av[4], bv[4];
#pragma unroll
        for (int j = 0; j < 4; j++) {
            int kc = k0 + acol0 + j * 4;
            av[j] = make_float4(0.f, 0.f, 0.f, 0.f);
            if (m0 + arow < M && kc < K)
                av[j] = *reinterpret_cast<const float4*>(&A[(size_t)(m0 + arow) * K + kc]);
        }
#pragma unroll
        for (int j = 0; j < 4; j++) {
            int kr = k0 + brow + j * 8;
            bv[j] = (kr < K) ? *reinterpret_cast<const float4*>(&B[(size_t)kr * 128 + bcol])
                             : make_float4(0.f, 0.f, 0.f, 0.f);
        }
        __syncthreads();
#pragma unroll
        for (int j = 0; j < 4; j++) {
            int kc = acol0 + j * 4;
            As[kc + 0][arow] = av[j].x;
            As[kc + 1][arow] = av[j].y;
            As[kc + 2][arow] = av[j].z;
            As[kc + 3][arow] = av[j].w;
            *reinterpret_cast<float4*>(&Bs[brow + j * 8][bcol]) = bv[j];
        }
        __syncthreads();

#pragma unroll
        for (int ks = 0; ks < 4; ks++) {
            int kb = ks * 8;
            unsigned ahi[2][4], alo[2][4];
#pragma unroll
            for (int mf = 0; mf < 2; mf++) {
                int rm = wm * 32 + mf * 16;
                tf32_split(As[kb + c    ][rm + g    ], ahi[mf][0], alo[mf][0]);
                tf32_split(As[kb + c    ][rm + g + 8], ahi[mf][1], alo[mf][1]);
                tf32_split(As[kb + c + 4][rm + g    ], ahi[mf][2], alo[mf][2]);
                tf32_split(As[kb + c + 4][rm + g + 8], ahi[mf][3], alo[mf][3]);
            }
#pragma unroll
            for (int nf = 0; nf < 8; nf++) {
                int cn = wn * 64 + nf * 8;
                unsigned bhi[2], blo[2];
                tf32_split(Bs[kb + c    ][cn + g], bhi[0], blo[0]);
                tf32_split(Bs[kb + c + 4][cn + g], bhi[1], blo[1]);
                // hi*hi
                mma_tf32(acc[0][nf], ahi[0], bhi);
                mma_tf32(acc[1][nf], ahi[1], bhi);
                // hi*lo
                mma_tf32(acc[0][nf], ahi[0], blo);
                mma_tf32(acc[1][nf], ahi[1], blo);
                // lo*hi
                mma_tf32(acc[0][nf], alo[0], bhi);
                mma_tf32(acc[1][nf], alo[1], bhi);
            }
        }
    }

    // epilogue: c0/c1 -> row rbase, cols 2c,2c+1 ; c2/c3 -> row rbase+8
#pragma unroll
    for (int mf = 0; mf < 2; mf++) {
        int rbase = m0 + wm * 32 + mf * 16 + g;
#pragma unroll
        for (int half = 0; half < 2; half++) {
            int row = rbase + half * 8;
            if (row >= M) continue;
#pragma unroll
            for (int nf = 0; nf < 8; nf++) {
                int col = wn * 64 + nf * 8 + 2 * c;
                float v0 = acc[mf][nf][half * 2 + 0];
                float v1 = acc[mf][nf][half * 2 + 1];
                if (MODE == M_BIAS) {
                    v0 += bias[col];
                    v1 += bias[col + 1];
                } else if (MODE == M_EDGE) {
                    const float* dp = &D[(size_t)row * 128 + col];
                    v0 = silu_f(v0 + dp[0]);
                    v1 = silu_f(v1 + dp[1]);
                } else if (MODE == M_ONA) {
                    v0 = silu_f(v0 + bias[col]);
                    v1 = silu_f(v1 + bias[col + 1]);
                } else {
                    const float* dp = &D[(size_t)row * 128 + col];
                    v0 = dp[0] + v0 + bias[col];
                    v1 = dp[1] + v1 + bias[col + 1];
                }
                float2 o; o.x = v0; o.y = v1;
                *reinterpret_cast<float2*>(&C[(size_t)row * 128 + col]) = o;
            }
        }
    }
}

// ---------------- output stores ----------------
__global__ void store_layer_kernel(float* __restrict__ out, int layer) {
    int i = blockIdx.x * blockDim.x + threadIdx.x;
    if (i < NN * DIMN) {
        int n = i >> 7, d = i & 127;
        out[NN * DIMN + n * 256 + layer * 128 + d] = d_zi[i];
    }
}

__global__ void store_final_kernel(float* __restrict__ out) {
    int i = blockIdx.x * blockDim.x + threadIdx.x;
    if (i < NN * DIMN) out[i] = d_zi[i];
}

// ---------------- launch ----------------
static void* sym_addr(const void* sym) {
    void* p = nullptr;
    cudaGetSymbolAddress(&p, sym);
    return p;
}

extern "C" void kernel_launch(void* const* d_in, const int* in_sizes, int n_in,
                              void* d_out, int out_size) {
    const int*   species = (const int*)d_in[0];
    const int*   esrc    = (const int*)d_in[1];
    const int*   edst    = (const int*)d_in[2];
    const float* dist    = (const float*)d_in[3];
    const float* sw      = (const float*)d_in[4];
    const float* Z       = (const float*)d_in[5];
    const float* Ws0     = (const float*)d_in[6];
    const float* bs0     = (const float*)d_in[7];
    const float* V0      = (const float*)d_in[8];
    const float* Ws1     = (const float*)d_in[9];
    const float* bs1     = (const float*)d_in[10];
    const float* V1      = (const float*)d_in[11];
    const float* Won_a   = (const float*)d_in[12];
    const float* bon_a   = (const float*)d_in[13];
    const float* Won_b   = (const float*)d_in[14];
    const float* bon_b   = (const float*)d_in[15];
    float* out = (float*)d_out;

    float* p_z0    = (float*)sym_addr(d_z0);
    float* p_zself = (float*)sym_addr(d_zself);
    float* p_G     = (float*)sym_addr(d_G);
    float* p_zi    = (float*)sym_addr(d_zi);
    float* p_h     = (float*)sym_addr(d_h);

    // setup (layer-independent)
    embed_kernel<<<(NN * ZD16 + 255) / 256, 256>>>(species, Z);
    coeff_kernel<<<(NE + 127) / 128, 128>>>(dist, sw);
    zero_counts_kernel<<<(NN + 255) / 256, 256>>>();
    hist_kernel<<<(NE + 255) / 256, 256>>>(esrc);
    scan_kernel<<<1, 1024>>>();
    scatter_kernel<<<(NE + 255) / 256, 256>>>(esrc);

    const int GB = (NN + 127) / 128;
    const int EL = (NN * DIMN + 255) / 256;

    // ---- layer 0 ----
    gemm_tc<M_BIAS><<<GB, 256>>>(p_z0, Ws0, nullptr, bs0, p_zself, NN, ZD16);
    gather0_kernel<<<NN, 256>>>(edst);
    gemm_tc<M_EDGE><<<GB, 256>>>(p_G, V0, p_zself, nullptr, p_zi, NN, NB16 * ZD16);
    for (int j = 0; j < 3; j++) {
        gemm_tc<M_ONA><<<GB, 256>>>(p_zi, Won_a + j * 16384, nullptr, bon_a + j * 128, p_h, NN, 128);
        gemm_tc<M_ONB><<<GB, 256>>>(p_h, Won_b + j * 16384, p_zi, bon_b + j * 128, p_zi, NN, 128);
    }
    store_layer_kernel<<<EL, 256>>>(out, 0);

    // ---- layer 1 ----
    gemm_tc<M_BIAS><<<GB, 256>>>(p_zi, Ws1, nullptr, bs1, p_zself, NN, 128);
    gather1_kernel<<<NN, 128>>>(edst);
    gemm_tc<M_EDGE><<<GB, 256>>>(p_G, V1, p_zself, nullptr, p_zi, NN, NB16 * DIMN);
    for (int j = 0; j < 3; j++) {
        gemm_tc<M_ONA><<<GB, 256>>>(p_zi, Won_a + (3 + j) * 16384, nullptr, bon_a + (3 + j) * 128, p_h, NN, 128);
        gemm_tc<M_ONB><<<GB, 256>>>(p_h, Won_b + (3 + j) * 16384, p_zi, bon_b + (3 + j) * 128, p_zi, NN, 128);
    }
    store_layer_kernel<<<EL, 256>>>(out, 1);
    store_final_kernel<<<EL, 256>>>(out);
}